// round 12
// baseline (speedup 1.0000x reference)
#include <cuda_runtime.h>
#include <cuda_bf16.h>
#include <cuda_fp16.h>
#include <cstdint>

#define NROWS 50000
#define MPAD  50048            // 391 * 128
#define NFEAT 512
#define HID   128
#define NEDGE 1600000

// ------------------------- scratch (device globals) -------------------------
__device__ float  g_xw[(size_t)NROWS * HID];     // SPMM2 out / GEMM2 A (fp32)
__device__ __half g_xw16[(size_t)NROWS * HID];   // GEMM1 out (fp16), SPMM1 gather
__device__ __half g_h16[(size_t)NROWS * HID];    // fp16 copy of h, SPMM2 gather
__device__ __nv_bfloat16 g_bh1[HID * NFEAT];     // W1^T hi  [128, 512]
__device__ __nv_bfloat16 g_bl1[HID * NFEAT];
__device__ __nv_bfloat16 g_bh2[NFEAT * HID];     // W2^T hi  [512, 128]
__device__ __nv_bfloat16 g_bl2[NFEAT * HID];
__device__ __align__(16) int2 g_e1[NEDGE];       // packed (col, val) per edge
__device__ __align__(16) int2 g_e2[NEDGE];
__device__ int   g_rs1[NROWS + 1];
__device__ int   g_rs2[NROWS + 1];
__device__ int   g_cnt[2 * NROWS];               // zero-init; re-zeroed by scan2
__device__ int   g_next[2 * NROWS];

// --------------------------- CSR build -----------------------------------
__global__ void k_hist2(const int* __restrict__ r1, const int* __restrict__ r2,
                        int* __restrict__ cnt) {
    long i = (long)blockIdx.x * blockDim.x + threadIdx.x;
    if (i < NEDGE)               atomicAdd(&cnt[r1[i]], 1);
    else if (i < 2L * NEDGE)     atomicAdd(&cnt[NROWS + r2[i - NEDGE]], 1);
}

// 2 blocks; block g scans cnt[g*NROWS..] -> rs_g (and next copy).
// Re-zeros cnt after reading so the next call starts from a clean histogram
// (cnt is statically zero-initialized for the first call).
__global__ __launch_bounds__(1024) void k_scan2(int* __restrict__ cnt,
                                                int* __restrict__ rs1,
                                                int* __restrict__ rs2,
                                                int* __restrict__ next) {
    __shared__ int wsum[32];
    __shared__ int carry;
    const int g = blockIdx.x;
    int* c = cnt + g * NROWS;
    int* rs = g ? rs2 : rs1;
    int* nx = next + g * NROWS;
    const int lane = threadIdx.x & 31;
    const int warp = threadIdx.x >> 5;
    if (threadIdx.x == 0) carry = 0;
    __syncthreads();
    for (int base = 0; base < NROWS; base += 1024) {
        int i = base + (int)threadIdx.x;
        int v = 0;
        if (i < NROWS) { v = c[i]; c[i] = 0; }
        int s = v;
        #pragma unroll
        for (int o = 1; o < 32; o <<= 1) {
            int t = __shfl_up_sync(0xffffffffu, s, o);
            if (lane >= o) s += t;
        }
        if (lane == 31) wsum[warp] = s;
        __syncthreads();
        if (warp == 0) {
            int ws = wsum[lane];
            #pragma unroll
            for (int o = 1; o < 32; o <<= 1) {
                int t = __shfl_up_sync(0xffffffffu, ws, o);
                if (lane >= o) ws += t;
            }
            wsum[lane] = ws;
        }
        __syncthreads();
        int excl = carry + (warp ? wsum[warp - 1] : 0) + s - v;
        if (i < NROWS) { rs[i] = excl; nx[i] = excl; }
        __syncthreads();
        if (threadIdx.x == 0) carry += wsum[31];
        __syncthreads();
    }
    if (threadIdx.x == 0) rs[NROWS] = carry;
}

// single-graph scatter (next offset selects counter bank)
__global__ void k_scatter1(const int* __restrict__ r, const int* __restrict__ c,
                           const float* __restrict__ v, int* __restrict__ next,
                           int2* __restrict__ e) {
    int i = blockIdx.x * blockDim.x + threadIdx.x;
    if (i < NEDGE) {
        int p = atomicAdd(&next[r[i]], 1);
        e[p] = make_int2(c[i], __float_as_int(v[i]));
    }
}

// --------------- both W splits in ONE kernel: W[K,N] -> Bh/Bl [N,K] ----------
__global__ void k_splitw_both(const float* __restrict__ W1f,
                              __nv_bfloat16* __restrict__ bh1,
                              __nv_bfloat16* __restrict__ bl1,
                              const float* __restrict__ W2f,
                              __nv_bfloat16* __restrict__ bh2,
                              __nv_bfloat16* __restrict__ bl2) {
    int i = blockIdx.x * blockDim.x + threadIdx.x;
    const int SZ = NFEAT * HID;
    if (i < SZ) {
        // W1: K=NFEAT rows, N=HID cols
        int k = i / HID, n = i % HID;
        float a = W1f[i];
        __nv_bfloat16 h = __float2bfloat16(a);
        bh1[(size_t)n * NFEAT + k] = h;
        bl1[(size_t)n * NFEAT + k] = __float2bfloat16(a - __bfloat162float(h));
    } else if (i < 2 * SZ) {
        // W2: K=HID rows, N=NFEAT cols
        int j = i - SZ;
        int k = j / NFEAT, n = j % NFEAT;
        float a = W2f[j];
        __nv_bfloat16 h = __float2bfloat16(a);
        bh2[(size_t)n * HID + k] = h;
        bl2[(size_t)n * HID + k] = __float2bfloat16(a - __bfloat162float(h));
    }
}

// ----------------- fused-split mma.sync bf16 GEMM (R5/R7-proven) --------------
// C[M,Nc] = A[M,K] fp32 @ (Bh+Bl)[Nc,K]^T, in-kernel A hi/lo split.
// OUTH: write fp16 output instead of fp32.
#define BK 32
#define SROW2 80
#define TILE2 (128 * SROW2)           // 10240
#define GSMEM2 (8 * TILE2)            // 81920

__device__ __forceinline__ uint32_t smem_u32(const void* p) {
    uint32_t a;
    asm("{ .reg .u64 t; cvta.to.shared.u64 t, %1; cvt.u32.u64 %0, t; }" : "=r"(a) : "l"(p));
    return a;
}
__device__ __forceinline__ void cpa16(uint32_t s, const void* g) {
    asm volatile("cp.async.cg.shared.global [%0], [%1], 16;" :: "r"(s), "l"(g));
}
__device__ __forceinline__ void ldm_x4(uint32_t* r, uint32_t a) {
    asm volatile("ldmatrix.sync.aligned.m8n8.x4.shared.b16 {%0,%1,%2,%3}, [%4];"
                 : "=r"(r[0]), "=r"(r[1]), "=r"(r[2]), "=r"(r[3]) : "r"(a));
}
__device__ __forceinline__ void ldm_x2(uint32_t* r, uint32_t a) {
    asm volatile("ldmatrix.sync.aligned.m8n8.x2.shared.b16 {%0,%1}, [%2];"
                 : "=r"(r[0]), "=r"(r[1]) : "r"(a));
}
__device__ __forceinline__ void mma16816(float* d, const uint32_t* a, const uint32_t* b) {
    asm volatile("mma.sync.aligned.m16n8k16.row.col.f32.bf16.bf16.f32 "
                 "{%0,%1,%2,%3}, {%4,%5,%6,%7}, {%8,%9}, {%0,%1,%2,%3};"
                 : "+f"(d[0]), "+f"(d[1]), "+f"(d[2]), "+f"(d[3])
                 : "r"(a[0]), "r"(a[1]), "r"(a[2]), "r"(a[3]), "r"(b[0]), "r"(b[1]));
}
__device__ __forceinline__ uint32_t pack_bf2(float x, float y) {
    __nv_bfloat162 t(__float2bfloat16(x), __float2bfloat16(y));
    return *(uint32_t*)&t;
}

template <bool EPI, bool OUTH>
__global__ void __launch_bounds__(256, 2) k_gemm_f(
    const float* __restrict__ A, const __nv_bfloat16* __restrict__ Bh,
    const __nv_bfloat16* __restrict__ Bl, void* __restrict__ Cv,
    int M, int Nc, int K, const float* __restrict__ bias) {
    extern __shared__ char sm[];
    const uint32_t s0 = smem_u32(sm);
    const uint32_t sAH0 = s0,              sAH1 = s0 + TILE2;
    const uint32_t sAL0 = s0 + 2 * TILE2,  sAL1 = s0 + 3 * TILE2;
    const uint32_t sBH0 = s0 + 4 * TILE2,  sBH1 = s0 + 5 * TILE2;
    const uint32_t sBL0 = s0 + 6 * TILE2,  sBL1 = s0 + 7 * TILE2;

    const int tid  = threadIdx.x;
    const int lane = tid & 31;
    const int wid  = tid >> 5;
    const int warpM = wid & 1;
    const int warpN = wid >> 1;
    const int rowBase = blockIdx.x * 128;
    const int colBase = blockIdx.y * 128;

    const int ar  = tid >> 3;
    const int ac4 = tid & 7;
    const int br = tid >> 1;
    const int b0 = (tid & 1) * 16;
    const char* gBh = (const char*)(Bh + (size_t)(colBase + br) * K);
    const char* gBl = (const char*)(Bl + (size_t)(colBase + br) * K);
    const uint32_t bDst = br * SROW2 + b0;

    const int nIter = K / BK;

    float4 ra[4];
    #pragma unroll
    for (int p = 0; p < 4; p++) {
        int row = rowBase + ar + p * 32;
        ra[p] = (row < M) ? *(const float4*)(A + (size_t)row * K + ac4 * 4)
                          : make_float4(0.f, 0.f, 0.f, 0.f);
    }
    cpa16(sBH0 + bDst,      gBh + b0);
    cpa16(sBH0 + bDst + 32, gBh + b0 + 32);
    cpa16(sBL0 + bDst,      gBl + b0);
    cpa16(sBL0 + bDst + 32, gBl + b0 + 32);
    asm volatile("cp.async.commit_group;");

    const int aRow = (lane & 7) + ((lane >> 3) & 1) * 8;
    const int aK   = ((lane >> 4) & 1) * 8;
    const int bRow = lane & 7;
    const int bK   = ((lane >> 3) & 1) * 8;
    const uint32_t aOff = (warpM * 64 + aRow) * SROW2 + aK * 2;
    const uint32_t bOff = (warpN * 32 + bRow) * SROW2 + bK * 2;

    float acc[4][4][4];
    #pragma unroll
    for (int i = 0; i < 4; i++)
        #pragma unroll
        for (int j = 0; j < 4; j++)
            #pragma unroll
            for (int q = 0; q < 4; q++) acc[i][j][q] = 0.f;

    for (int it = 0; it < nIter; it++) {
        const int cur = it & 1;
        const uint32_t aH = cur ? sAH1 : sAH0;
        const uint32_t aL = cur ? sAL1 : sAL0;
        const uint32_t bH = cur ? sBH1 : sBH0;
        const uint32_t bL = cur ? sBL1 : sBL0;

        #pragma unroll
        for (int p = 0; p < 4; p++) {
            float4 v = ra[p];
            uint32_t h01 = pack_bf2(v.x, v.y);
            uint32_t h23 = pack_bf2(v.z, v.w);
            float hx = __bfloat162float(__float2bfloat16(v.x));
            float hy = __bfloat162float(__float2bfloat16(v.y));
            float hz = __bfloat162float(__float2bfloat16(v.z));
            float hw = __bfloat162float(__float2bfloat16(v.w));
            uint32_t l01 = pack_bf2(v.x - hx, v.y - hy);
            uint32_t l23 = pack_bf2(v.z - hz, v.w - hw);
            uint32_t dst = (uint32_t)(ar + p * 32) * SROW2 + ac4 * 8;
            asm volatile("st.shared.v2.b32 [%0], {%1,%2};" :: "r"(aH + dst), "r"(h01), "r"(h23));
            asm volatile("st.shared.v2.b32 [%0], {%1,%2};" :: "r"(aL + dst), "r"(l01), "r"(l23));
        }

        if (it + 1 < nIter) {
            const uint32_t nBH = cur ? sBH0 : sBH1;
            const uint32_t nBL = cur ? sBL0 : sBL1;
            const size_t ko = (size_t)(it + 1) * 64;
            cpa16(nBH + bDst,      gBh + ko + b0);
            cpa16(nBH + bDst + 32, gBh + ko + b0 + 32);
            cpa16(nBL + bDst,      gBl + ko + b0);
            cpa16(nBL + bDst + 32, gBl + ko + b0 + 32);
            asm volatile("cp.async.commit_group;");
            const int kf = (it + 1) * 32 + ac4 * 4;
            #pragma unroll
            for (int p = 0; p < 4; p++) {
                int row = rowBase + ar + p * 32;
                ra[p] = (row < M) ? *(const float4*)(A + (size_t)row * K + kf)
                                  : make_float4(0.f, 0.f, 0.f, 0.f);
            }
            asm volatile("cp.async.wait_group 1;");
        } else {
            asm volatile("cp.async.wait_group 0;");
        }
        __syncthreads();

        #pragma unroll
        for (int kb = 0; kb < 2; kb++) {
            uint32_t bfH[4][2], bfL[4][2];
            #pragma unroll
            for (int j = 0; j < 4; j++) {
                ldm_x2(bfH[j], bH + bOff + j * 8 * SROW2 + kb * 32);
                ldm_x2(bfL[j], bL + bOff + j * 8 * SROW2 + kb * 32);
            }
            #pragma unroll
            for (int i = 0; i < 4; i++) {
                uint32_t afH[4], afL[4];
                ldm_x4(afH, aH + aOff + i * 16 * SROW2 + kb * 32);
                ldm_x4(afL, aL + aOff + i * 16 * SROW2 + kb * 32);
                #pragma unroll
                for (int j = 0; j < 4; j++) {
                    mma16816(acc[i][j], afH, bfH[j]);
                    mma16816(acc[i][j], afH, bfL[j]);
                    mma16816(acc[i][j], afL, bfH[j]);
                }
            }
        }
        __syncthreads();
    }

    #pragma unroll
    for (int i = 0; i < 4; i++) {
        int r0 = rowBase + warpM * 64 + i * 16 + (lane >> 2);
        #pragma unroll
        for (int j = 0; j < 4; j++) {
            int c0 = colBase + warpN * 32 + j * 8 + (lane & 3) * 2;
            float2 v0 = make_float2(acc[i][j][0], acc[i][j][1]);
            float2 v1 = make_float2(acc[i][j][2], acc[i][j][3]);
            if (EPI) {
                float2 b = *(const float2*)(bias + c0);
                v0.x = fmaxf(v0.x + b.x, 0.f); v0.y = fmaxf(v0.y + b.y, 0.f);
                v1.x = fmaxf(v1.x + b.x, 0.f); v1.y = fmaxf(v1.y + b.y, 0.f);
            }
            if (OUTH) {
                __half* C = (__half*)Cv;
                __half2 q0 = __floats2half2_rn(v0.x, v0.y);
                __half2 q1 = __floats2half2_rn(v1.x, v1.y);
                if (r0 < M)     *(__half2*)(C + (size_t)r0 * Nc + c0)       = q0;
                if (r0 + 8 < M) *(__half2*)(C + (size_t)(r0 + 8) * Nc + c0) = q1;
            } else {
                float* C = (float*)Cv;
                if (r0 < M)     *(float2*)(C + (size_t)r0 * Nc + c0)       = v0;
                if (r0 + 8 < M) *(float2*)(C + (size_t)(r0 + 8) * Nc + c0) = v1;
            }
        }
    }
}

// ------------------------------ SPMM (D=128) --------------------------------
// fp16 gather, fp32 accumulate. EPI: bias+relu. Writes fp32 out (optional) and
// fp16 out16 (optional).
template <bool EPI>
__global__ __launch_bounds__(256) void k_spmm_f16(
    const int* __restrict__ rs, const int2* __restrict__ ev,
    const __half* __restrict__ dense16, const float* __restrict__ bias,
    float* __restrict__ out, __half* __restrict__ out16) {
    int row = (blockIdx.x * blockDim.x + threadIdx.x) >> 5;
    int lane = threadIdx.x & 31;
    if (row >= NROWS) return;
    int s = rs[row], e = rs[row + 1];
    float4 acc = make_float4(0.f, 0.f, 0.f, 0.f);
    for (int i = s; i < e; i++) {
        int2 p = __ldg(&ev[i]);
        float v = __int_as_float(p.y);
        uint2 q = *(const uint2*)(dense16 + (size_t)p.x * HID + lane * 4);
        float2 f0 = __half22float2(*(__half2*)&q.x);
        float2 f1 = __half22float2(*(__half2*)&q.y);
        acc.x = fmaf(v, f0.x, acc.x);
        acc.y = fmaf(v, f0.y, acc.y);
        acc.z = fmaf(v, f1.x, acc.z);
        acc.w = fmaf(v, f1.y, acc.w);
    }
    if (EPI) {
        float4 b = ((const float4*)bias)[lane];
        acc.x = fmaxf(acc.x + b.x, 0.f);
        acc.y = fmaxf(acc.y + b.y, 0.f);
        acc.z = fmaxf(acc.z + b.z, 0.f);
        acc.w = fmaxf(acc.w + b.w, 0.f);
    }
    if (out)
        ((float4*)(out + (size_t)row * HID))[lane] = acc;
    if (out16) {
        __half2 ha = __floats2half2_rn(acc.x, acc.y);
        __half2 hb = __floats2half2_rn(acc.z, acc.w);
        uint2 q = make_uint2(*(uint32_t*)&ha, *(uint32_t*)&hb);
        *(uint2*)(out16 + (size_t)row * HID + lane * 4) = q;
    }
}

// ------------------------------ launch --------------------------------------
extern "C" void kernel_launch(void* const* d_in, const int* in_sizes, int n_in,
                              void* d_out, int out_size) {
    const float* x           = (const float*)d_in[0];
    const int*   adj_row     = (const int*)d_in[1];
    const int*   adj_col     = (const int*)d_in[2];
    const float* adj_val     = (const float*)d_in[3];
    const int*   adj_inv_row = (const int*)d_in[4];
    const int*   adj_inv_col = (const int*)d_in[5];
    const float* adj_inv_val = (const float*)d_in[6];
    const float* W1          = (const float*)d_in[7];
    const float* b1          = (const float*)d_in[8];
    const float* W2          = (const float*)d_in[9];
    const float* b2          = (const float*)d_in[10];

    float* out = (float*)d_out;                   // [N, NFEAT]
    float* h   = out + (size_t)NROWS * NFEAT;     // [N, HID]

    float* xw;
    __half *xw16, *h16;
    __nv_bfloat16 *bh1, *bl1, *bh2, *bl2;
    int2 *e1, *e2;
    int *rs1, *rs2, *cnt, *next;
    cudaGetSymbolAddress((void**)&xw,   g_xw);
    cudaGetSymbolAddress((void**)&xw16, g_xw16);
    cudaGetSymbolAddress((void**)&h16,  g_h16);
    cudaGetSymbolAddress((void**)&bh1,  g_bh1);
    cudaGetSymbolAddress((void**)&bl1,  g_bl1);
    cudaGetSymbolAddress((void**)&bh2,  g_bh2);
    cudaGetSymbolAddress((void**)&bl2,  g_bl2);
    cudaGetSymbolAddress((void**)&e1,   g_e1);
    cudaGetSymbolAddress((void**)&e2,   g_e2);
    cudaGetSymbolAddress((void**)&rs1,  g_rs1);
    cudaGetSymbolAddress((void**)&rs2,  g_rs2);
    cudaGetSymbolAddress((void**)&cnt,  g_cnt);
    cudaGetSymbolAddress((void**)&next, g_next);

    cudaFuncSetAttribute(k_gemm_f<false, true>,
                         cudaFuncAttributeMaxDynamicSharedMemorySize, GSMEM2);
    cudaFuncSetAttribute(k_gemm_f<true, false>,
                         cudaFuncAttributeMaxDynamicSharedMemorySize, GSMEM2);

    // one-time side stream + events (no device memory involved)
    static cudaStream_t sSide = nullptr;
    static cudaEvent_t evFork = nullptr, evScan = nullptr, evG1 = nullptr, evS2 = nullptr;
    if (!sSide) {
        cudaStreamCreateWithFlags(&sSide, cudaStreamNonBlocking);
        cudaEventCreateWithFlags(&evFork, cudaEventDisableTiming);
        cudaEventCreateWithFlags(&evScan, cudaEventDisableTiming);
        cudaEventCreateWithFlags(&evG1,   cudaEventDisableTiming);
        cudaEventCreateWithFlags(&evS2,   cudaEventDisableTiming);
    }

    const int TB = 256;
    const int gE  = (NEDGE + TB - 1) / TB;

    // ---- fork ----
    cudaEventRecord(evFork, 0);
    cudaStreamWaitEvent(sSide, evFork, 0);

    // side stream: fused weight split + GEMM1 (fp16 output)
    k_splitw_both<<<(2 * NFEAT * HID + TB - 1) / TB, TB, 0, sSide>>>(
        W1, bh1, bl1, W2, bh2, bl2);
    {
        dim3 grid(MPAD / 128, HID / 128);
        k_gemm_f<false, true><<<grid, 256, GSMEM2, sSide>>>(
            x, bh1, bl1, xw16, NROWS, HID, NFEAT, nullptr);
    }
    cudaEventRecord(evG1, sSide);

    // main stream: CSR (cnt is pre-zeroed: static init / re-zeroed by scan2)
    k_hist2<<<(int)((2L * NEDGE + TB - 1) / TB), TB>>>(adj_row, adj_inv_row, cnt);
    k_scan2<<<2, 1024>>>(cnt, rs1, rs2, next);
    cudaEventRecord(evScan, 0);
    k_scatter1<<<gE, TB>>>(adj_row, adj_col, adj_val, next, e1);

    // side stream: graph-2 scatter (after scan + GEMM1) overlaps SPMM1
    cudaStreamWaitEvent(sSide, evScan, 0);
    k_scatter1<<<gE, TB, 0, sSide>>>(adj_inv_row, adj_inv_col, adj_inv_val,
                                     next + NROWS, e2);
    cudaEventRecord(evS2, sSide);

    // main: SPMM1 gathers fp16 xw16, writes fp32 h (output) + fp16 h16
    cudaStreamWaitEvent(0, evG1, 0);
    k_spmm_f16<true><<<(NROWS * 32 + TB - 1) / TB, TB>>>(rs1, e1, xw16, b1, h, h16);

    // main: SPMM2 gathers fp16 h16, writes fp32 g into xw
    cudaStreamWaitEvent(0, evS2, 0);
    k_spmm_f16<false><<<(NROWS * 32 + TB - 1) / TB, TB>>>(rs2, e2, h16, nullptr,
                                                          xw, (__half*)nullptr);

    // GEMM2: out = relu(g @ W2 + b2)
    {
        dim3 grid(MPAD / 128, NFEAT / 128);
        k_gemm_f<true, false><<<grid, 256, GSMEM2>>>(xw, bh2, bl2, out,
                                                     NROWS, NFEAT, HID, b2);
    }
}

// round 13
// speedup vs baseline: 1.1726x; 1.1726x over previous
#include <cuda_runtime.h>
#include <cuda_bf16.h>
#include <cuda_fp16.h>
#include <cstdint>

#define NROWS 50000
#define MPAD  50048            // 391 * 128
#define NFEAT 512
#define HID   128
#define NEDGE 1600000
#define SCSEG 4096
#define NBLK  13               // ceil(50000/4096)

// ------------------------- scratch (device globals) -------------------------
__device__ float  g_xw[(size_t)NROWS * HID];
__device__ __half g_h16[(size_t)NROWS * HID];   // fp16 copy of h for SPMM2 gather
__device__ __nv_bfloat16 g_bh1[HID * NFEAT];    // W1^T hi  [128, 512]
__device__ __nv_bfloat16 g_bl1[HID * NFEAT];
__device__ __nv_bfloat16 g_bh2[NFEAT * HID];    // W2^T hi  [512, 128]
__device__ __nv_bfloat16 g_bl2[NFEAT * HID];
__device__ __align__(16) int2 g_e1[NEDGE];      // packed (col, val) per edge
__device__ __align__(16) int2 g_e2[NEDGE];
__device__ int   g_rs1[NROWS + 1];
__device__ int   g_rs2[NROWS + 1];
__device__ __align__(16) int g_cnt[2 * NROWS];  // zero-init; re-zeroed by scanC
__device__ __align__(16) int g_next[2 * NROWS];
__device__ int   g_part[2 * 16];                // per-block partial sums

// --------------------------- CSR build -----------------------------------
__global__ void k_hist2(const int* __restrict__ r1, const int* __restrict__ r2,
                        int* __restrict__ cnt) {
    long i = (long)blockIdx.x * blockDim.x + threadIdx.x;
    if (i < NEDGE)               atomicAdd(&cnt[r1[i]], 1);
    else if (i < 2L * NEDGE)     atomicAdd(&cnt[NROWS + r2[i - NEDGE]], 1);
}

// Pass A: per-block (4096-elem segment) sums. grid (NBLK, 2).
__global__ __launch_bounds__(1024) void k_scanA(const int* __restrict__ cnt,
                                                int* __restrict__ part) {
    __shared__ int wsum[32];
    const int g = blockIdx.y, b = blockIdx.x;
    const int* c = cnt + g * NROWS;
    int i = b * SCSEG + (int)threadIdx.x * 4;
    int4 v = make_int4(0, 0, 0, 0);
    if (i < NROWS) v = *(const int4*)(c + i);
    int t = v.x + v.y + v.z + v.w;
    #pragma unroll
    for (int o = 16; o > 0; o >>= 1) t += __shfl_down_sync(0xffffffffu, t, o);
    if ((threadIdx.x & 31) == 0) wsum[threadIdx.x >> 5] = t;
    __syncthreads();
    if (threadIdx.x < 32) {
        int u = wsum[threadIdx.x];
        #pragma unroll
        for (int o = 16; o > 0; o >>= 1) u += __shfl_down_sync(0xffffffffu, u, o);
        if (threadIdx.x == 0) part[g * 16 + b] = u;
    }
}

// Pass B: exclusive-scan the NBLK partials per graph; write totals. 64 threads.
__global__ void k_scanB(int* __restrict__ part, int* __restrict__ rs1,
                        int* __restrict__ rs2) {
    int g = threadIdx.x >> 5, lane = threadIdx.x & 31;
    if (g >= 2) return;
    int v = (lane < NBLK) ? part[g * 16 + lane] : 0;
    int s = v;
    #pragma unroll
    for (int o = 1; o < 32; o <<= 1) {
        int t = __shfl_up_sync(0xffffffffu, s, o);
        if (lane >= o) s += t;
    }
    if (lane < NBLK) part[g * 16 + lane] = s - v;    // exclusive
    int total = __shfl_sync(0xffffffffu, s, NBLK - 1);
    if (lane == 0) (g ? rs2 : rs1)[NROWS] = total;
}

// Pass C: block-local exclusive scan + offset; writes rs & next; zeros cnt.
__global__ __launch_bounds__(1024) void k_scanC(int* __restrict__ cnt,
                                                const int* __restrict__ part,
                                                int* __restrict__ rs1,
                                                int* __restrict__ rs2,
                                                int* __restrict__ next) {
    __shared__ int wsum[32];
    const int g = blockIdx.y, b = blockIdx.x;
    int* c = cnt + g * NROWS;
    int* rs = g ? rs2 : rs1;
    int* nx = next + g * NROWS;
    const int lane = threadIdx.x & 31;
    const int warp = threadIdx.x >> 5;
    int i = b * SCSEG + (int)threadIdx.x * 4;
    int4 v = make_int4(0, 0, 0, 0);
    if (i < NROWS) { v = *(int4*)(c + i); *(int4*)(c + i) = make_int4(0, 0, 0, 0); }
    int tsum = v.x + v.y + v.z + v.w;
    int s = tsum;
    #pragma unroll
    for (int o = 1; o < 32; o <<= 1) {
        int t = __shfl_up_sync(0xffffffffu, s, o);
        if (lane >= o) s += t;
    }
    if (lane == 31) wsum[warp] = s;
    __syncthreads();
    if (warp == 0) {
        int ws = wsum[lane];
        #pragma unroll
        for (int o = 1; o < 32; o <<= 1) {
            int t = __shfl_up_sync(0xffffffffu, ws, o);
            if (lane >= o) ws += t;
        }
        wsum[lane] = ws;
    }
    __syncthreads();
    int excl = (warp ? wsum[warp - 1] : 0) + (s - tsum) + part[g * 16 + b];
    if (i < NROWS) {
        int e0 = excl;
        int e1 = e0 + v.x;
        int e2 = e1 + v.y;
        int e3 = e2 + v.z;
        int4 w = make_int4(e0, e1, e2, e3);
        *(int4*)(rs + i) = w;
        *(int4*)(nx + i) = w;
    }
}

// single-graph scatter (next offset selects counter bank)
__global__ void k_scatter1(const int* __restrict__ r, const int* __restrict__ c,
                           const float* __restrict__ v, int* __restrict__ next,
                           int2* __restrict__ e) {
    int i = blockIdx.x * blockDim.x + threadIdx.x;
    if (i < NEDGE) {
        int p = atomicAdd(&next[r[i]], 1);
        e[p] = make_int2(c[i], __float_as_int(v[i]));
    }
}

// --------------- both W splits in ONE kernel: W[K,N] -> Bh/Bl [N,K] ----------
__global__ void k_splitw_both(const float* __restrict__ W1f,
                              __nv_bfloat16* __restrict__ bh1,
                              __nv_bfloat16* __restrict__ bl1,
                              const float* __restrict__ W2f,
                              __nv_bfloat16* __restrict__ bh2,
                              __nv_bfloat16* __restrict__ bl2) {
    int i = blockIdx.x * blockDim.x + threadIdx.x;
    const int SZ = NFEAT * HID;
    if (i < SZ) {
        int k = i / HID, n = i % HID;
        float a = W1f[i];
        __nv_bfloat16 h = __float2bfloat16(a);
        bh1[(size_t)n * NFEAT + k] = h;
        bl1[(size_t)n * NFEAT + k] = __float2bfloat16(a - __bfloat162float(h));
    } else if (i < 2 * SZ) {
        int j = i - SZ;
        int k = j / NFEAT, n = j % NFEAT;
        float a = W2f[j];
        __nv_bfloat16 h = __float2bfloat16(a);
        bh2[(size_t)n * HID + k] = h;
        bl2[(size_t)n * HID + k] = __float2bfloat16(a - __bfloat162float(h));
    }
}

// ----------------- fused-split mma.sync bf16 GEMM (R5/R7-proven) --------------
#define BK 32
#define SROW2 80
#define TILE2 (128 * SROW2)
#define GSMEM2 (8 * TILE2)

__device__ __forceinline__ uint32_t smem_u32(const void* p) {
    uint32_t a;
    asm("{ .reg .u64 t; cvta.to.shared.u64 t, %1; cvt.u32.u64 %0, t; }" : "=r"(a) : "l"(p));
    return a;
}
__device__ __forceinline__ void cpa16(uint32_t s, const void* g) {
    asm volatile("cp.async.cg.shared.global [%0], [%1], 16;" :: "r"(s), "l"(g));
}
__device__ __forceinline__ void ldm_x4(uint32_t* r, uint32_t a) {
    asm volatile("ldmatrix.sync.aligned.m8n8.x4.shared.b16 {%0,%1,%2,%3}, [%4];"
                 : "=r"(r[0]), "=r"(r[1]), "=r"(r[2]), "=r"(r[3]) : "r"(a));
}
__device__ __forceinline__ void ldm_x2(uint32_t* r, uint32_t a) {
    asm volatile("ldmatrix.sync.aligned.m8n8.x2.shared.b16 {%0,%1}, [%2];"
                 : "=r"(r[0]), "=r"(r[1]) : "r"(a));
}
__device__ __forceinline__ void mma16816(float* d, const uint32_t* a, const uint32_t* b) {
    asm volatile("mma.sync.aligned.m16n8k16.row.col.f32.bf16.bf16.f32 "
                 "{%0,%1,%2,%3}, {%4,%5,%6,%7}, {%8,%9}, {%0,%1,%2,%3};"
                 : "+f"(d[0]), "+f"(d[1]), "+f"(d[2]), "+f"(d[3])
                 : "r"(a[0]), "r"(a[1]), "r"(a[2]), "r"(a[3]), "r"(b[0]), "r"(b[1]));
}
__device__ __forceinline__ uint32_t pack_bf2(float x, float y) {
    __nv_bfloat162 t(__float2bfloat16(x), __float2bfloat16(y));
    return *(uint32_t*)&t;
}

template <bool EPI>
__global__ void __launch_bounds__(256, 2) k_gemm_f(
    const float* __restrict__ A, const __nv_bfloat16* __restrict__ Bh,
    const __nv_bfloat16* __restrict__ Bl, float* __restrict__ C,
    int M, int Nc, int K, const float* __restrict__ bias) {
    extern __shared__ char sm[];
    const uint32_t s0 = smem_u32(sm);
    const uint32_t sAH0 = s0,              sAH1 = s0 + TILE2;
    const uint32_t sAL0 = s0 + 2 * TILE2,  sAL1 = s0 + 3 * TILE2;
    const uint32_t sBH0 = s0 + 4 * TILE2,  sBH1 = s0 + 5 * TILE2;
    const uint32_t sBL0 = s0 + 6 * TILE2,  sBL1 = s0 + 7 * TILE2;

    const int tid  = threadIdx.x;
    const int lane = tid & 31;
    const int wid  = tid >> 5;
    const int warpM = wid & 1;
    const int warpN = wid >> 1;
    const int rowBase = blockIdx.x * 128;
    const int colBase = blockIdx.y * 128;

    const int ar  = tid >> 3;
    const int ac4 = tid & 7;
    const int br = tid >> 1;
    const int b0 = (tid & 1) * 16;
    const char* gBh = (const char*)(Bh + (size_t)(colBase + br) * K);
    const char* gBl = (const char*)(Bl + (size_t)(colBase + br) * K);
    const uint32_t bDst = br * SROW2 + b0;

    const int nIter = K / BK;

    float4 ra[4];
    #pragma unroll
    for (int p = 0; p < 4; p++) {
        int row = rowBase + ar + p * 32;
        ra[p] = (row < M) ? *(const float4*)(A + (size_t)row * K + ac4 * 4)
                          : make_float4(0.f, 0.f, 0.f, 0.f);
    }
    cpa16(sBH0 + bDst,      gBh + b0);
    cpa16(sBH0 + bDst + 32, gBh + b0 + 32);
    cpa16(sBL0 + bDst,      gBl + b0);
    cpa16(sBL0 + bDst + 32, gBl + b0 + 32);
    asm volatile("cp.async.commit_group;");

    const int aRow = (lane & 7) + ((lane >> 3) & 1) * 8;
    const int aK   = ((lane >> 4) & 1) * 8;
    const int bRow = lane & 7;
    const int bK   = ((lane >> 3) & 1) * 8;
    const uint32_t aOff = (warpM * 64 + aRow) * SROW2 + aK * 2;
    const uint32_t bOff = (warpN * 32 + bRow) * SROW2 + bK * 2;

    float acc[4][4][4];
    #pragma unroll
    for (int i = 0; i < 4; i++)
        #pragma unroll
        for (int j = 0; j < 4; j++)
            #pragma unroll
            for (int q = 0; q < 4; q++) acc[i][j][q] = 0.f;

    for (int it = 0; it < nIter; it++) {
        const int cur = it & 1;
        const uint32_t aH = cur ? sAH1 : sAH0;
        const uint32_t aL = cur ? sAL1 : sAL0;
        const uint32_t bH = cur ? sBH1 : sBH0;
        const uint32_t bL = cur ? sBL1 : sBL0;

        #pragma unroll
        for (int p = 0; p < 4; p++) {
            float4 v = ra[p];
            uint32_t h01 = pack_bf2(v.x, v.y);
            uint32_t h23 = pack_bf2(v.z, v.w);
            float hx = __bfloat162float(__float2bfloat16(v.x));
            float hy = __bfloat162float(__float2bfloat16(v.y));
            float hz = __bfloat162float(__float2bfloat16(v.z));
            float hw = __bfloat162float(__float2bfloat16(v.w));
            uint32_t l01 = pack_bf2(v.x - hx, v.y - hy);
            uint32_t l23 = pack_bf2(v.z - hz, v.w - hw);
            uint32_t dst = (uint32_t)(ar + p * 32) * SROW2 + ac4 * 8;
            asm volatile("st.shared.v2.b32 [%0], {%1,%2};" :: "r"(aH + dst), "r"(h01), "r"(h23));
            asm volatile("st.shared.v2.b32 [%0], {%1,%2};" :: "r"(aL + dst), "r"(l01), "r"(l23));
        }

        if (it + 1 < nIter) {
            const uint32_t nBH = cur ? sBH0 : sBH1;
            const uint32_t nBL = cur ? sBL0 : sBL1;
            const size_t ko = (size_t)(it + 1) * 64;
            cpa16(nBH + bDst,      gBh + ko + b0);
            cpa16(nBH + bDst + 32, gBh + ko + b0 + 32);
            cpa16(nBL + bDst,      gBl + ko + b0);
            cpa16(nBL + bDst + 32, gBl + ko + b0 + 32);
            asm volatile("cp.async.commit_group;");
            const int kf = (it + 1) * 32 + ac4 * 4;
            #pragma unroll
            for (int p = 0; p < 4; p++) {
                int row = rowBase + ar + p * 32;
                ra[p] = (row < M) ? *(const float4*)(A + (size_t)row * K + kf)
                                  : make_float4(0.f, 0.f, 0.f, 0.f);
            }
            asm volatile("cp.async.wait_group 1;");
        } else {
            asm volatile("cp.async.wait_group 0;");
        }
        __syncthreads();

        #pragma unroll
        for (int kb = 0; kb < 2; kb++) {
            uint32_t bfH[4][2], bfL[4][2];
            #pragma unroll
            for (int j = 0; j < 4; j++) {
                ldm_x2(bfH[j], bH + bOff + j * 8 * SROW2 + kb * 32);
                ldm_x2(bfL[j], bL + bOff + j * 8 * SROW2 + kb * 32);
            }
            #pragma unroll
            for (int i = 0; i < 4; i++) {
                uint32_t afH[4], afL[4];
                ldm_x4(afH, aH + aOff + i * 16 * SROW2 + kb * 32);
                ldm_x4(afL, aL + aOff + i * 16 * SROW2 + kb * 32);
                #pragma unroll
                for (int j = 0; j < 4; j++) {
                    mma16816(acc[i][j], afH, bfH[j]);
                    mma16816(acc[i][j], afH, bfL[j]);
                    mma16816(acc[i][j], afL, bfH[j]);
                }
            }
        }
        __syncthreads();
    }

    #pragma unroll
    for (int i = 0; i < 4; i++) {
        int r0 = rowBase + warpM * 64 + i * 16 + (lane >> 2);
        #pragma unroll
        for (int j = 0; j < 4; j++) {
            int c0 = colBase + warpN * 32 + j * 8 + (lane & 3) * 2;
            float2 v0 = make_float2(acc[i][j][0], acc[i][j][1]);
            float2 v1 = make_float2(acc[i][j][2], acc[i][j][3]);
            if (EPI) {
                float2 b = *(const float2*)(bias + c0);
                v0.x = fmaxf(v0.x + b.x, 0.f); v0.y = fmaxf(v0.y + b.y, 0.f);
                v1.x = fmaxf(v1.x + b.x, 0.f); v1.y = fmaxf(v1.y + b.y, 0.f);
            }
            if (r0 < M)     *(float2*)(C + (size_t)r0 * Nc + c0)       = v0;
            if (r0 + 8 < M) *(float2*)(C + (size_t)(r0 + 8) * Nc + c0) = v1;
        }
    }
}

// ------------------------------ SPMM (D=128) --------------------------------
// SPMM1: fp32 gather, bias+relu, writes fp32 h AND fp16 h16 copy (R11-proven)
__global__ __launch_bounds__(256) void k_spmm1(
    const int* __restrict__ rs, const int2* __restrict__ ev,
    const float* __restrict__ dense, const float* __restrict__ bias,
    float* __restrict__ out, __half* __restrict__ out16) {
    int row = (blockIdx.x * blockDim.x + threadIdx.x) >> 5;
    int lane = threadIdx.x & 31;
    if (row >= NROWS) return;
    int s = rs[row], e = rs[row + 1];
    float4 acc = make_float4(0.f, 0.f, 0.f, 0.f);
    for (int i = s; i < e; i++) {
        int2 p = __ldg(&ev[i]);
        float v = __int_as_float(p.y);
        float4 d = ((const float4*)(dense + (size_t)p.x * HID))[lane];
        acc.x = fmaf(v, d.x, acc.x);
        acc.y = fmaf(v, d.y, acc.y);
        acc.z = fmaf(v, d.z, acc.z);
        acc.w = fmaf(v, d.w, acc.w);
    }
    float4 b = ((const float4*)bias)[lane];
    acc.x = fmaxf(acc.x + b.x, 0.f);
    acc.y = fmaxf(acc.y + b.y, 0.f);
    acc.z = fmaxf(acc.z + b.z, 0.f);
    acc.w = fmaxf(acc.w + b.w, 0.f);
    ((float4*)(out + (size_t)row * HID))[lane] = acc;
    __half2 ha = __floats2half2_rn(acc.x, acc.y);
    __half2 hb = __floats2half2_rn(acc.z, acc.w);
    uint2 q = make_uint2(*(uint32_t*)&ha, *(uint32_t*)&hb);
    *(uint2*)(out16 + (size_t)row * HID + lane * 4) = q;
}

// SPMM2: fp16 gather, fp32 accumulate (R11-proven)
__global__ __launch_bounds__(256) void k_spmm2_f16(
    const int* __restrict__ rs, const int2* __restrict__ ev,
    const __half* __restrict__ dense16, float* __restrict__ out) {
    int row = (blockIdx.x * blockDim.x + threadIdx.x) >> 5;
    int lane = threadIdx.x & 31;
    if (row >= NROWS) return;
    int s = rs[row], e = rs[row + 1];
    float4 acc = make_float4(0.f, 0.f, 0.f, 0.f);
    for (int i = s; i < e; i++) {
        int2 p = __ldg(&ev[i]);
        float v = __int_as_float(p.y);
        uint2 q = *(const uint2*)(dense16 + (size_t)p.x * HID + lane * 4);
        float2 f0 = __half22float2(*(__half2*)&q.x);
        float2 f1 = __half22float2(*(__half2*)&q.y);
        acc.x = fmaf(v, f0.x, acc.x);
        acc.y = fmaf(v, f0.y, acc.y);
        acc.z = fmaf(v, f1.x, acc.z);
        acc.w = fmaf(v, f1.y, acc.w);
    }
    ((float4*)(out + (size_t)row * HID))[lane] = acc;
}

// ------------------------------ launch --------------------------------------
extern "C" void kernel_launch(void* const* d_in, const int* in_sizes, int n_in,
                              void* d_out, int out_size) {
    const float* x           = (const float*)d_in[0];
    const int*   adj_row     = (const int*)d_in[1];
    const int*   adj_col     = (const int*)d_in[2];
    const float* adj_val     = (const float*)d_in[3];
    const int*   adj_inv_row = (const int*)d_in[4];
    const int*   adj_inv_col = (const int*)d_in[5];
    const float* adj_inv_val = (const float*)d_in[6];
    const float* W1          = (const float*)d_in[7];
    const float* b1          = (const float*)d_in[8];
    const float* W2          = (const float*)d_in[9];
    const float* b2          = (const float*)d_in[10];

    float* out = (float*)d_out;                   // [N, NFEAT]
    float* h   = out + (size_t)NROWS * NFEAT;     // [N, HID]

    float* xw;
    __half* h16;
    __nv_bfloat16 *bh1, *bl1, *bh2, *bl2;
    int2 *e1, *e2;
    int *rs1, *rs2, *cnt, *next, *part;
    cudaGetSymbolAddress((void**)&xw,   g_xw);
    cudaGetSymbolAddress((void**)&h16,  g_h16);
    cudaGetSymbolAddress((void**)&bh1,  g_bh1);
    cudaGetSymbolAddress((void**)&bl1,  g_bl1);
    cudaGetSymbolAddress((void**)&bh2,  g_bh2);
    cudaGetSymbolAddress((void**)&bl2,  g_bl2);
    cudaGetSymbolAddress((void**)&e1,   g_e1);
    cudaGetSymbolAddress((void**)&e2,   g_e2);
    cudaGetSymbolAddress((void**)&rs1,  g_rs1);
    cudaGetSymbolAddress((void**)&rs2,  g_rs2);
    cudaGetSymbolAddress((void**)&cnt,  g_cnt);
    cudaGetSymbolAddress((void**)&next, g_next);
    cudaGetSymbolAddress((void**)&part, g_part);

    cudaFuncSetAttribute(k_gemm_f<false>,
                         cudaFuncAttributeMaxDynamicSharedMemorySize, GSMEM2);
    cudaFuncSetAttribute(k_gemm_f<true>,
                         cudaFuncAttributeMaxDynamicSharedMemorySize, GSMEM2);

    static cudaStream_t sSide = nullptr;
    static cudaEvent_t evFork = nullptr, evScan = nullptr, evG1 = nullptr, evS2 = nullptr;
    if (!sSide) {
        cudaStreamCreateWithFlags(&sSide, cudaStreamNonBlocking);
        cudaEventCreateWithFlags(&evFork, cudaEventDisableTiming);
        cudaEventCreateWithFlags(&evScan, cudaEventDisableTiming);
        cudaEventCreateWithFlags(&evG1,   cudaEventDisableTiming);
        cudaEventCreateWithFlags(&evS2,   cudaEventDisableTiming);
    }

    const int TB = 256;
    const int gE = (NEDGE + TB - 1) / TB;

    // ---- fork ----
    cudaEventRecord(evFork, 0);
    cudaStreamWaitEvent(sSide, evFork, 0);

    // side stream: fused weight split + GEMM1 (fp32 out, R11 config)
    k_splitw_both<<<(2 * NFEAT * HID + TB - 1) / TB, TB, 0, sSide>>>(
        W1, bh1, bl1, W2, bh2, bl2);
    {
        dim3 grid(MPAD / 128, HID / 128);
        k_gemm_f<false><<<grid, 256, GSMEM2, sSide>>>(x, bh1, bl1, xw,
                                                      NROWS, HID, NFEAT, nullptr);
    }
    cudaEventRecord(evG1, sSide);

    // main stream: CSR — hist, 3-pass parallel scan, graph-1 scatter
    k_hist2<<<(int)((2L * NEDGE + TB - 1) / TB), TB>>>(adj_row, adj_inv_row, cnt);
    {
        dim3 gAB(NBLK, 2);
        k_scanA<<<gAB, 1024>>>(cnt, part);
        k_scanB<<<1, 64>>>(part, rs1, rs2);
        k_scanC<<<gAB, 1024>>>(cnt, part, rs1, rs2, next);
    }
    cudaEventRecord(evScan, 0);
    k_scatter1<<<gE, TB>>>(adj_row, adj_col, adj_val, next, e1);

    // side stream: graph-2 scatter (after scan + GEMM1) overlaps SPMM1
    cudaStreamWaitEvent(sSide, evScan, 0);
    k_scatter1<<<gE, TB, 0, sSide>>>(adj_inv_row, adj_inv_col, adj_inv_val,
                                     next + NROWS, e2);
    cudaEventRecord(evS2, sSide);

    // main: SPMM1 (fp32 gather) writes h + h16
    cudaStreamWaitEvent(0, evG1, 0);
    k_spmm1<<<(NROWS * 32 + TB - 1) / TB, TB>>>(rs1, e1, xw, b1, h, h16);

    // main: SPMM2 (fp16 gather) writes fp32 g into xw
    cudaStreamWaitEvent(0, evS2, 0);
    k_spmm2_f16<<<(NROWS * 32 + TB - 1) / TB, TB>>>(rs2, e2, h16, xw);

    // GEMM2: out = relu(g @ W2 + b2)
    {
        dim3 grid(MPAD / 128, NFEAT / 128);
        k_gemm_f<true><<<grid, 256, GSMEM2>>>(xw, bh2, bl2, out, NROWS, NFEAT, HID, b2);
    }
}